// round 12
// baseline (speedup 1.0000x reference)
#include <cuda_runtime.h>

// Hand_Input_Sorter — v12: persistent grid-stride variant of the measured
// optimum (v10). Same per-group code (warp handles 2 adjacent frames, float2
// loads/stores with default cache policy, shuffle-realized swap), but a single
// wave of 148x8 CTAs loops over groups instead of 16,384 one-shot CTAs,
// eliminating wave-transition and CTA launch overhead.

static constexpr int FRAME_LEN = 130;
static constexpr unsigned FULL = 0xFFFFFFFFu;

__device__ __forceinline__ bool compute_skip(float h0, float p0, float h1, float p1)
{
    bool nan0 = isnan(h0);
    bool nan1 = isnan(h1);
    bool skip = (h1 > h0);                 // false if either NaN (IEEE, matches jnp)
    skip |= (nan0 && nan1);                // both missing
    skip |= (nan0 && (h1 == 1.0f));        // only hand1, labeled right
    skip |= (nan1 && (h0 == 0.0f));        // only hand0, labeled left
    if (!nan0 && !nan1 && (h0 == h1)) {
        skip |= ((h0 == 0.0f) && (p0 > p1));
        skip |= ((h0 == 1.0f) && (p0 < p1));
    }
    return skip;
}

// Pairs: a = pair[lane] (elems 2l,2l+1), b = pair[lane+32] (elems 64+2l,65+2l),
// c = pair[64] (elems 128,129), loaded uniformly on all lanes.
__device__ __forceinline__ void store_frame(float* __restrict__ o, int lane,
                                            float2 a, float2 b, float2 c, bool skip)
{
    float2* __restrict__ o2 = (float2*)o;
    if (skip) {
        o2[lane]      = a;
        o2[lane + 32] = b;
        if (lane == 0) o2[64] = c;
    } else {
        // out[j] = X[j+65] (j<65) / X[j-65] (j>=65), as float2 slots:
        // slot lane:    {b.y, b[lane+1].x} with b[32] := c
        float bx_next = __shfl_down_sync(FULL, b.x, 1);
        float2 v0 = make_float2(b.y, (lane == 31) ? c.x : bx_next);
        // slot lane+32: lane0 -> {c.y, a[0].x}; else {a[lane-1].y, a.x}
        float ay_prev = __shfl_up_sync(FULL, a.y, 1);
        float a0x     = __shfl_sync(FULL, a.x, 0);
        float2 v1 = (lane == 0) ? make_float2(c.y, a0x)
                                : make_float2(ay_prev, a.x);
        // slot 64: {a[31].y, b[0].x}
        float ay31 = __shfl_sync(FULL, a.y, 31);
        float b0x  = __shfl_sync(FULL, b.x, 0);
        o2[lane]      = v0;
        o2[lane + 32] = v1;
        if (lane == 0) o2[64] = make_float2(ay31, b0x);
    }
}

__device__ __forceinline__ void process_group(const float* __restrict__ X,
                                              float* __restrict__ out,
                                              int f0, int n_frames, int lane)
{
    const bool has2 = (f0 + 1) < n_frames;

    const float2* __restrict__ i0 = (const float2*)(X + (size_t)f0 * FRAME_LEN);
    const float2* __restrict__ i1 = (const float2*)(X + (size_t)(f0 + 1) * FRAME_LEN);

    // Front-batch all loads; default cache policy.
    float2 a0 = __ldg(&i0[lane]);
    float2 b0 = __ldg(&i0[lane + 32]);
    float2 c0 = __ldg(&i0[64]);
    float2 a1 = make_float2(0.f, 0.f), b1 = a1, c1 = a1;
    if (has2) {
        a1 = __ldg(&i1[lane]);
        b1 = __ldg(&i1[lane + 32]);
        c1 = __ldg(&i1[64]);
    }

    // h0=a.x@0, p0=a.y@0, h1=elem65=b.y@0, p1=elem66=b.x@1
    bool skip0 = compute_skip(__shfl_sync(FULL, a0.x, 0), __shfl_sync(FULL, a0.y, 0),
                              __shfl_sync(FULL, b0.y, 0), __shfl_sync(FULL, b0.x, 1));
    bool skip1 = false;
    if (has2)
        skip1 = compute_skip(__shfl_sync(FULL, a1.x, 0), __shfl_sync(FULL, a1.y, 0),
                             __shfl_sync(FULL, b1.y, 0), __shfl_sync(FULL, b1.x, 1));

    store_frame(out + (size_t)f0 * FRAME_LEN, lane, a0, b0, c0, skip0);
    if (has2)
        store_frame(out + (size_t)(f0 + 1) * FRAME_LEN, lane, a1, b1, c1, skip1);
}

__global__ __launch_bounds__(256) void hand_sorter_v12(
    const float* __restrict__ X,
    float* __restrict__ out,
    int n_frames)
{
    const int lane     = threadIdx.x & 31;
    const int warp_id  = blockIdx.x * (blockDim.x >> 5) + (threadIdx.x >> 5);
    const int n_warps  = gridDim.x * (blockDim.x >> 5);
    const int n_groups = (n_frames + 1) >> 1;

    for (int g = warp_id; g < n_groups; g += n_warps)
        process_group(X, out, g * 2, n_frames, lane);
}

extern "C" void kernel_launch(void* const* d_in, const int* in_sizes, int n_in,
                              void* d_out, int out_size)
{
    const float* X = (const float*)d_in[0];
    // d_in[1] (swap_pattern int32[130]) is the fixed 65<->65 half swap; computed
    // analytically, so it isn't gathered.
    float* out = (float*)d_out;

    int n_frames = in_sizes[0] / FRAME_LEN;
    int n_groups = (n_frames + 1) >> 1;

    const int threads = 256;
    const int wpb = threads / 32;
    // One resident wave: 148 SMs x 8 CTAs (256 thr, 32 regs -> 2048 thr/SM).
    int blocks = 148 * 8;
    int max_blocks = (n_groups + wpb - 1) / wpb;
    if (blocks > max_blocks) blocks = max_blocks;

    hand_sorter_v12<<<blocks, threads>>>(X, out, n_frames);
}

// round 13
// speedup vs baseline: 1.1453x; 1.1453x over previous
#include <cuda_runtime.h>

// Hand_Input_Sorter — FINAL kernel (v10, measured optimum; v12 persistent
// variant regressed and is reverted).
//
// Per-frame conditional 65<->65 half-swap of [*,130] fp32.
//   - one-shot grid, warp-per-frame, 2 adjacent frames per warp (shared 128B
//     boundary sectors of the 520B-stride frames hit L2 from the neighbor)
//   - front-batched float2 loads (6 LDG.64/lane), DEFAULT cache policy
//     (.cs measured slower on both loads and stores)
//   - aligned float2 stores on BOTH paths; swap permutation realized in
//     registers via warp shuffles (misaligned scattered stores measured slower,
//     full float4 alignment via shuffles also measured slower)
//   - 256-thread blocks (measured faster than 512; persistent grid-stride
//     measured slower: loop serializes cross-group MLP)
//
// Measured: device 36.38us ~ 7.5 TB/s effective unique-byte throughput
// (~94% of 8 TB/s HBM spec) — practical wall for this layout.

static constexpr int FRAME_LEN = 130;
static constexpr unsigned FULL = 0xFFFFFFFFu;

__device__ __forceinline__ bool compute_skip(float h0, float p0, float h1, float p1)
{
    bool nan0 = isnan(h0);
    bool nan1 = isnan(h1);
    bool skip = (h1 > h0);                 // false if either NaN (IEEE, matches jnp)
    skip |= (nan0 && nan1);                // both missing
    skip |= (nan0 && (h1 == 1.0f));        // only hand1, labeled right
    skip |= (nan1 && (h0 == 0.0f));        // only hand0, labeled left
    if (!nan0 && !nan1 && (h0 == h1)) {
        skip |= ((h0 == 0.0f) && (p0 > p1));
        skip |= ((h0 == 1.0f) && (p0 < p1));
    }
    return skip;
}

// Pairs: a = pair[lane] (elems 2l,2l+1), b = pair[lane+32] (elems 64+2l,65+2l),
// c = pair[64] (elems 128,129), loaded uniformly on all lanes.
__device__ __forceinline__ void store_frame(float* __restrict__ o, int lane,
                                            float2 a, float2 b, float2 c, bool skip)
{
    float2* __restrict__ o2 = (float2*)o;
    if (skip) {
        o2[lane]      = a;
        o2[lane + 32] = b;
        if (lane == 0) o2[64] = c;
    } else {
        // out[j] = X[j+65] (j<65) / X[j-65] (j>=65), as float2 slots:
        // slot lane:    {b.y, b[lane+1].x} with b[32] := c
        float bx_next = __shfl_down_sync(FULL, b.x, 1);
        float2 v0 = make_float2(b.y, (lane == 31) ? c.x : bx_next);
        // slot lane+32: lane0 -> {c.y, a[0].x}; else {a[lane-1].y, a.x}
        float ay_prev = __shfl_up_sync(FULL, a.y, 1);
        float a0x     = __shfl_sync(FULL, a.x, 0);
        float2 v1 = (lane == 0) ? make_float2(c.y, a0x)
                                : make_float2(ay_prev, a.x);
        // slot 64: {a[31].y, b[0].x}
        float ay31 = __shfl_sync(FULL, a.y, 31);
        float b0x  = __shfl_sync(FULL, b.x, 0);
        o2[lane]      = v0;
        o2[lane + 32] = v1;
        if (lane == 0) o2[64] = make_float2(ay31, b0x);
    }
}

__global__ __launch_bounds__(256) void hand_sorter_final(
    const float* __restrict__ X,
    float* __restrict__ out,
    int n_frames)
{
    const int gw   = blockIdx.x * (blockDim.x >> 5) + (threadIdx.x >> 5);
    const int lane = threadIdx.x & 31;
    const int f0   = gw * 2;
    if (f0 >= n_frames) return;
    const bool has2 = (f0 + 1) < n_frames;

    const float2* __restrict__ i0 = (const float2*)(X + (size_t)f0 * FRAME_LEN);
    const float2* __restrict__ i1 = (const float2*)(X + (size_t)(f0 + 1) * FRAME_LEN);

    // Front-batch all loads; default cache policy.
    float2 a0 = __ldg(&i0[lane]);
    float2 b0 = __ldg(&i0[lane + 32]);
    float2 c0 = __ldg(&i0[64]);
    float2 a1 = make_float2(0.f, 0.f), b1 = a1, c1 = a1;
    if (has2) {
        a1 = __ldg(&i1[lane]);
        b1 = __ldg(&i1[lane + 32]);
        c1 = __ldg(&i1[64]);
    }

    // h0=a.x@0, p0=a.y@0, h1=elem65=b.y@0, p1=elem66=b.x@1
    bool skip0 = compute_skip(__shfl_sync(FULL, a0.x, 0), __shfl_sync(FULL, a0.y, 0),
                              __shfl_sync(FULL, b0.y, 0), __shfl_sync(FULL, b0.x, 1));
    bool skip1 = false;
    if (has2)
        skip1 = compute_skip(__shfl_sync(FULL, a1.x, 0), __shfl_sync(FULL, a1.y, 0),
                             __shfl_sync(FULL, b1.y, 0), __shfl_sync(FULL, b1.x, 1));

    store_frame(out + (size_t)f0 * FRAME_LEN, lane, a0, b0, c0, skip0);
    if (has2)
        store_frame(out + (size_t)(f0 + 1) * FRAME_LEN, lane, a1, b1, c1, skip1);
}

extern "C" void kernel_launch(void* const* d_in, const int* in_sizes, int n_in,
                              void* d_out, int out_size)
{
    const float* X = (const float*)d_in[0];
    // d_in[1] (swap_pattern int32[130]) is the fixed 65<->65 half swap; computed
    // analytically, so it isn't gathered.
    float* out = (float*)d_out;

    int n_frames = in_sizes[0] / FRAME_LEN;
    int n_warps  = (n_frames + 1) / 2;
    const int threads = 256;
    int warps_per_block = threads / 32;
    int blocks = (n_warps + warps_per_block - 1) / warps_per_block;

    hand_sorter_final<<<blocks, threads>>>(X, out, n_frames);
}

// round 14
// speedup vs baseline: 1.1461x; 1.0007x over previous
#include <cuda_runtime.h>

// Hand_Input_Sorter — FINAL family (v10 + predicate-shuffle reduction).
//
// Per-frame conditional 65<->65 half-swap of [*,130] fp32.
//   - one-shot grid, 2 adjacent frames per warp, 256-thread blocks
//   - front-batched float2 loads / aligned float2 stores, default cache policy
//   - swap permutation realized in registers via warp shuffles
//   - predicate: h0,p0,h1 already live on lane 0; only p1 is shuffled in, and
//     lane 0's skip boolean is broadcast (2 shuffles/frame instead of 4)
//
// Measured family optimum: device 36.4-37.1us ~ 7.5 TB/s effective (~94% of
// HBM spec). All structural / cache-policy / grid-shape alternatives measured
// slower (smem staging, float4+shuffle alignment, .cs hints, persistent grid).

static constexpr int FRAME_LEN = 130;
static constexpr unsigned FULL = 0xFFFFFFFFu;

__device__ __forceinline__ bool compute_skip(float h0, float p0, float h1, float p1)
{
    bool nan0 = isnan(h0);
    bool nan1 = isnan(h1);
    bool skip = (h1 > h0);                 // false if either NaN (IEEE, matches jnp)
    skip |= (nan0 && nan1);                // both missing
    skip |= (nan0 && (h1 == 1.0f));        // only hand1, labeled right
    skip |= (nan1 && (h0 == 0.0f));        // only hand0, labeled left
    if (!nan0 && !nan1 && (h0 == h1)) {
        skip |= ((h0 == 0.0f) && (p0 > p1));
        skip |= ((h0 == 1.0f) && (p0 < p1));
    }
    return skip;
}

// Lane-local predicate + single broadcast: h0=a.x, p0=a.y, h1=b.y are lane 0's
// own registers; p1=b.x@1 is shuffled in. Every lane evaluates compute_skip on
// its local values (garbage off lane 0); only lane 0's result is broadcast.
__device__ __forceinline__ bool frame_skip(float2 a, float2 b)
{
    float p1 = __shfl_sync(FULL, b.x, 1);
    bool local = compute_skip(a.x, a.y, b.y, p1);
    return (bool)__shfl_sync(FULL, (int)local, 0);
}

// Pairs: a = pair[lane] (elems 2l,2l+1), b = pair[lane+32] (elems 64+2l,65+2l),
// c = pair[64] (elems 128,129), loaded uniformly on all lanes.
__device__ __forceinline__ void store_frame(float* __restrict__ o, int lane,
                                            float2 a, float2 b, float2 c, bool skip)
{
    float2* __restrict__ o2 = (float2*)o;
    if (skip) {
        o2[lane]      = a;
        o2[lane + 32] = b;
        if (lane == 0) o2[64] = c;
    } else {
        // out[j] = X[j+65] (j<65) / X[j-65] (j>=65), as float2 slots:
        // slot lane:    {b.y, b[lane+1].x} with b[32] := c
        float bx_next = __shfl_down_sync(FULL, b.x, 1);
        float2 v0 = make_float2(b.y, (lane == 31) ? c.x : bx_next);
        // slot lane+32: lane0 -> {c.y, a[0].x}; else {a[lane-1].y, a.x}
        float ay_prev = __shfl_up_sync(FULL, a.y, 1);
        float a0x     = __shfl_sync(FULL, a.x, 0);
        float2 v1 = (lane == 0) ? make_float2(c.y, a0x)
                                : make_float2(ay_prev, a.x);
        // slot 64: {a[31].y, b[0].x}
        float ay31 = __shfl_sync(FULL, a.y, 31);
        float b0x  = __shfl_sync(FULL, b.x, 0);
        o2[lane]      = v0;
        o2[lane + 32] = v1;
        if (lane == 0) o2[64] = make_float2(ay31, b0x);
    }
}

__global__ __launch_bounds__(256) void hand_sorter_v14(
    const float* __restrict__ X,
    float* __restrict__ out,
    int n_frames)
{
    const int gw   = blockIdx.x * (blockDim.x >> 5) + (threadIdx.x >> 5);
    const int lane = threadIdx.x & 31;
    const int f0   = gw * 2;
    if (f0 >= n_frames) return;
    const bool has2 = (f0 + 1) < n_frames;

    const float2* __restrict__ i0 = (const float2*)(X + (size_t)f0 * FRAME_LEN);
    const float2* __restrict__ i1 = (const float2*)(X + (size_t)(f0 + 1) * FRAME_LEN);

    // Front-batch all loads; default cache policy.
    float2 a0 = __ldg(&i0[lane]);
    float2 b0 = __ldg(&i0[lane + 32]);
    float2 c0 = __ldg(&i0[64]);
    float2 a1 = make_float2(0.f, 0.f), b1 = a1, c1 = a1;
    if (has2) {
        a1 = __ldg(&i1[lane]);
        b1 = __ldg(&i1[lane + 32]);
        c1 = __ldg(&i1[64]);
    }

    bool skip0 = frame_skip(a0, b0);
    bool skip1 = has2 ? frame_skip(a1, b1) : false;

    store_frame(out + (size_t)f0 * FRAME_LEN, lane, a0, b0, c0, skip0);
    if (has2)
        store_frame(out + (size_t)(f0 + 1) * FRAME_LEN, lane, a1, b1, c1, skip1);
}

extern "C" void kernel_launch(void* const* d_in, const int* in_sizes, int n_in,
                              void* d_out, int out_size)
{
    const float* X = (const float*)d_in[0];
    // d_in[1] (swap_pattern int32[130]) is the fixed 65<->65 half swap; computed
    // analytically, so it isn't gathered.
    float* out = (float*)d_out;

    int n_frames = in_sizes[0] / FRAME_LEN;
    int n_warps  = (n_frames + 1) / 2;
    const int threads = 256;
    int warps_per_block = threads / 32;
    int blocks = (n_warps + warps_per_block - 1) / warps_per_block;

    hand_sorter_v14<<<blocks, threads>>>(X, out, n_frames);
}